// round 7
// baseline (speedup 1.0000x reference)
#include <cuda_runtime.h>

#define BB 2
#define SS 2048
#define DD 256
#define HH 8
#define DHD 32

// Scratch (allocation-free: device globals)
__device__ float g_q[BB*HH*SS*DHD];
__device__ float g_k[BB*HH*SS*DHD];
__device__ float g_v[BB*HH*SS*DHD];
__device__ float g_ctx[BB*SS*DD];

// ---------------------------------------------------------------------------
// QKV projection: Y = X @ W^T + b for wq/wk/wv, stored head-major [B,H,S,32]
// GEMM M=4096, N=768 (q|k|v), K=256. BM=BN=64, BK=32, 256 threads, 4x4 micro.
// ---------------------------------------------------------------------------
__global__ __launch_bounds__(256) void qkv_kernel(
    const float* __restrict__ x,
    const float* __restrict__ wq, const float* __restrict__ bq,
    const float* __restrict__ wk, const float* __restrict__ bk,
    const float* __restrict__ wv, const float* __restrict__ bv)
{
    __shared__ float As[32][68];
    __shared__ float Bs[32][68];
    const int mt = blockIdx.x * 64;
    const int nt = blockIdx.y * 64;          // 0..767
    const int wsel = nt >> 8;                // 0=q,1=k,2=v
    const int nw = nt & 255;
    const float* W    = (wsel == 0) ? wq : ((wsel == 1) ? wk : wv);
    const float* bias = (wsel == 0) ? bq : ((wsel == 1) ? bk : bv);
    float* dst        = (wsel == 0) ? g_q : ((wsel == 1) ? g_k : g_v);

    const int tid = threadIdx.x;
    const int ty = tid >> 4, tx = tid & 15;
    float acc[4][4] = {};

    for (int k0 = 0; k0 < 256; k0 += 32) {
        for (int t = tid; t < 64 * 32; t += 256) {
            int m = t >> 5, kk = t & 31;
            As[kk][m] = x[(size_t)(mt + m) * 256 + k0 + kk];
            Bs[kk][m] = W[(size_t)(nw + m) * 256 + k0 + kk];
        }
        __syncthreads();
        #pragma unroll
        for (int kk = 0; kk < 32; kk++) {
            float4 a4 = *(const float4*)&As[kk][ty * 4];
            float4 b4 = *(const float4*)&Bs[kk][tx * 4];
            float a[4] = {a4.x, a4.y, a4.z, a4.w};
            float b[4] = {b4.x, b4.y, b4.z, b4.w};
            #pragma unroll
            for (int i = 0; i < 4; i++)
                #pragma unroll
                for (int j = 0; j < 4; j++)
                    acc[i][j] += a[i] * b[j];
        }
        __syncthreads();
    }
    #pragma unroll
    for (int i = 0; i < 4; i++) {
        int m = mt + ty * 4 + i;
        int bidx = m >> 11, s = m & 2047;
        #pragma unroll
        for (int j = 0; j < 4; j++) {
            int n = nw + tx * 4 + j;
            int h = n >> 5, dh = n & 31;
            dst[(((size_t)(bidx * HH + h) * SS + s) * DHD) + dh] = acc[i][j] + bias[n];
        }
    }
}

// ---------------------------------------------------------------------------
// Output projection: out = ctx @ wc^T + bc.  M=4096, N=256, K=256.
// ---------------------------------------------------------------------------
__global__ __launch_bounds__(256) void proj_kernel(
    const float* __restrict__ wc, const float* __restrict__ bc,
    float* __restrict__ out)
{
    __shared__ float As[32][68];
    __shared__ float Bs[32][68];
    const int mt = blockIdx.x * 64;
    const int nw = blockIdx.y * 64;
    const int tid = threadIdx.x;
    const int ty = tid >> 4, tx = tid & 15;
    float acc[4][4] = {};

    for (int k0 = 0; k0 < 256; k0 += 32) {
        for (int t = tid; t < 64 * 32; t += 256) {
            int m = t >> 5, kk = t & 31;
            As[kk][m] = g_ctx[(size_t)(mt + m) * 256 + k0 + kk];
            Bs[kk][m] = wc[(size_t)(nw + m) * 256 + k0 + kk];
        }
        __syncthreads();
        #pragma unroll
        for (int kk = 0; kk < 32; kk++) {
            float4 a4 = *(const float4*)&As[kk][ty * 4];
            float4 b4 = *(const float4*)&Bs[kk][tx * 4];
            float a[4] = {a4.x, a4.y, a4.z, a4.w};
            float b[4] = {b4.x, b4.y, b4.z, b4.w};
            #pragma unroll
            for (int i = 0; i < 4; i++)
                #pragma unroll
                for (int j = 0; j < 4; j++)
                    acc[i][j] += a[i] * b[j];
        }
        __syncthreads();
    }
    #pragma unroll
    for (int i = 0; i < 4; i++) {
        int m = mt + ty * 4 + i;
        #pragma unroll
        for (int j = 0; j < 4; j++) {
            int n = nw + tx * 4 + j;
            out[(size_t)m * 256 + n] = acc[i][j] + bc[n];
        }
    }
}

// ---------------------------------------------------------------------------
// Attention: one block per (b, 16-row q tile), loops over all 8 heads.
// Full 16x2048 score row kept in smem -> exact softmax, head-mean accumulated
// into the block-exclusive d_out slice (L2 resident), PV fused, P never hits
// HBM.
// smem layout (floats): sS[16*2048]=32768 | sKV[512*33]=16896 | sQ[16*33]=528
// ---------------------------------------------------------------------------
#define SMEM_FLOATS (32768 + 16896 + 528)

__global__ __launch_bounds__(256) void attn_kernel(float* __restrict__ attn_out)
{
    extern __shared__ float sm[];
    float* sS = sm;                     // 16 x 2048 scores/probs
    float* sK = sm + 32768;             // 512 x 33 K tile (aliased: V tile, reduce buf)
    float* sQ = sm + 32768 + 16896;     // 16 x 33
    __shared__ float s_invl[16];

    const int tid = threadIdx.x;
    const int b  = blockIdx.x >> 7;
    const int q0 = (blockIdx.x & 127) << 4;

    float* ap = attn_out + (size_t)(b * SS + q0) * SS;

    for (int h = 0; h < HH; h++) {
        const float* qb = g_q + ((size_t)(b * HH + h) * SS + q0) * DHD;
        const float* kb = g_k + (size_t)(b * HH + h) * SS * DHD;
        const float* vb = g_v + (size_t)(b * HH + h) * SS * DHD;

        // --- load Q tile (16x32) ---
        for (int t = tid; t < 16 * 32; t += 256)
            sQ[(t >> 5) * 33 + (t & 31)] = qb[t];

        // --- scores: S = Q K^T * scale, k-tiles of 512, micro 4q x 8k ---
        const int qg = tid >> 6;      // 0..3 -> 4 q rows each
        const int kg = tid & 63;      // k columns kg + 64*m
        const float scale = 0.17677669529663687f; // 1/sqrt(32)
        for (int kt = 0; kt < 4; kt++) {
            __syncthreads();  // prior consumers of sK (and sQ writers on kt==0) done
            for (int t = tid; t < 512 * 8; t += 256) {
                float4 v4 = *(const float4*)(kb + (size_t)kt * 16384 + (size_t)t * 4);
                int row = t >> 3, d4 = (t & 7) * 4;
                float* p = &sK[row * 33 + d4];
                p[0] = v4.x; p[1] = v4.y; p[2] = v4.z; p[3] = v4.w;
            }
            __syncthreads();
            float acc[4][8] = {};
            #pragma unroll
            for (int d = 0; d < 32; d++) {
                float a[4], bv[8];
                #pragma unroll
                for (int i = 0; i < 4; i++) a[i] = sQ[(qg * 4 + i) * 33 + d];
                #pragma unroll
                for (int m = 0; m < 8; m++) bv[m] = sK[(kg + 64 * m) * 33 + d];
                #pragma unroll
                for (int i = 0; i < 4; i++)
                    #pragma unroll
                    for (int m = 0; m < 8; m++)
                        acc[i][m] += a[i] * bv[m];
            }
            #pragma unroll
            for (int i = 0; i < 4; i++)
                #pragma unroll
                for (int m = 0; m < 8; m++)
                    sS[(qg * 4 + i) * 2048 + kt * 512 + kg + 64 * m] = acc[i][m] * scale;
        }
        __syncthreads();

        // --- softmax over full row (exact, in smem) ---
        {
            const int row = tid >> 4, j = tid & 15;   // 16 threads per row
            float4* r4 = (float4*)(sS + row * 2048);
            float mx = -1e30f;
            for (int k = j; k < 512; k += 16) {
                float4 v = r4[k];
                mx = fmaxf(mx, fmaxf(fmaxf(v.x, v.y), fmaxf(v.z, v.w)));
            }
            #pragma unroll
            for (int o = 8; o; o >>= 1) mx = fmaxf(mx, __shfl_xor_sync(0xffffffffu, mx, o));
            float sum = 0.f;
            for (int k = j; k < 512; k += 16) {
                float4 v = r4[k];
                v.x = __expf(v.x - mx); v.y = __expf(v.y - mx);
                v.z = __expf(v.z - mx); v.w = __expf(v.w - mx);
                sum += v.x + v.y + v.z + v.w;
                r4[k] = v;
            }
            #pragma unroll
            for (int o = 8; o; o >>= 1) sum += __shfl_xor_sync(0xffffffffu, sum, o);
            if (j == 0) s_invl[row] = 1.0f / sum;
        }
        __syncthreads();

        // --- accumulate head-mean attention into d_out slice (block-exclusive) ---
        {
            const float4* s4 = (const float4*)sS;
            float4* a4 = (float4*)ap;
            for (int t = tid; t < 16 * 512; t += 256) {
                int r = t >> 9;
                float f = s_invl[r] * 0.125f;
                float4 v = s4[t];
                v.x *= f; v.y *= f; v.z *= f; v.w *= f;
                if (h == 0) {
                    a4[t] = v;
                } else {
                    float4 o = a4[t];
                    o.x += v.x; o.y += v.y; o.z += v.z; o.w += v.w;
                    a4[t] = o;
                }
            }
        }

        // --- PV: O = P V, 4 phases of 512 k, micro 4q x 4d, k split 8 ways ---
        float accO[4][4] = {};
        const int qg2 = tid >> 6;          // 4 q rows
        const int ks  = (tid >> 3) & 7;    // k stripe (mod 8)
        const int dg  = tid & 7;           // 4 d cols
        for (int p = 0; p < 4; p++) {
            __syncthreads();  // previous phase consumers of sK done
            for (int t = tid; t < 512 * 8; t += 256) {
                float4 v4 = *(const float4*)(vb + (size_t)p * 16384 + (size_t)t * 4);
                int row = t >> 3, d4 = (t & 7) * 4;
                float* pp = &sK[row * 33 + d4];
                pp[0] = v4.x; pp[1] = v4.y; pp[2] = v4.z; pp[3] = v4.w;
            }
            __syncthreads();
            #pragma unroll 4
            for (int kk = 0; kk < 64; kk++) {
                int k = kk * 8 + ks;
                float pv[4], vv[4];
                #pragma unroll
                for (int i = 0; i < 4; i++) pv[i] = sS[(qg2 * 4 + i) * 2048 + p * 512 + k];
                #pragma unroll
                for (int j = 0; j < 4; j++) vv[j] = sK[k * 33 + dg * 4 + j];
                #pragma unroll
                for (int i = 0; i < 4; i++)
                    #pragma unroll
                    for (int j = 0; j < 4; j++)
                        accO[i][j] += pv[i] * vv[j];
            }
        }
        __syncthreads();
        // reduce the 8 k-stripes via smem (alias sK region)
        float* sRed = sK;
        #pragma unroll
        for (int i = 0; i < 4; i++)
            #pragma unroll
            for (int j = 0; j < 4; j++)
                sRed[((qg2 * 4 + i) * 32 + dg * 4 + j) * 8 + ks] = accO[i][j];
        __syncthreads();
        for (int o = tid; o < 512; o += 256) {
            int r = o >> 5, d = o & 31;
            float s = 0.f;
            #pragma unroll
            for (int e = 0; e < 8; e++) s += sRed[o * 8 + e];
            g_ctx[(size_t)(b * SS + q0 + r) * DD + h * DHD + d] = s * s_invl[r];
        }
        __syncthreads();  // protect sRed/sQ/sS before next head
    }
}

// ---------------------------------------------------------------------------
extern "C" void kernel_launch(void* const* d_in, const int* in_sizes, int n_in,
                              void* d_out, int out_size)
{
    const float* x  = (const float*)d_in[0];
    const float* wq = (const float*)d_in[1];
    const float* bq = (const float*)d_in[2];
    const float* wk = (const float*)d_in[3];
    const float* bk = (const float*)d_in[4];
    const float* wv = (const float*)d_in[5];
    const float* bv = (const float*)d_in[6];
    const float* wc = (const float*)d_in[7];
    const float* bc = (const float*)d_in[8];

    float* out  = (float*)d_out;
    float* attn = out + (size_t)BB * SS * DD;   // [B,S,S] region after [B,S,D]

    qkv_kernel<<<dim3(64, 12), 256>>>(x, wq, bq, wk, bk, wv, bv);

    cudaFuncSetAttribute(attn_kernel,
                         cudaFuncAttributeMaxDynamicSharedMemorySize,
                         SMEM_FLOATS * (int)sizeof(float));
    attn_kernel<<<256, 256, SMEM_FLOATS * sizeof(float)>>>(attn);

    proj_kernel<<<dim3(64, 4), 256>>>(wc, bc, out);
}

// round 8
// speedup vs baseline: 1.0454x; 1.0454x over previous
#include <cuda_runtime.h>

#define BB 2
#define SS 2048
#define DD 256
#define HH 8
#define DHD 32

// Scratch (allocation-free: device globals)
__device__ float g_q[BB*HH*SS*DHD];
__device__ float g_k[BB*HH*SS*DHD];
__device__ float g_v[BB*HH*SS*DHD];
__device__ float g_ctx[BB*SS*DD];

// ---------------------------------------------------------------------------
// QKV projection: Y = X @ W^T + b for wq/wk/wv, stored head-major [B,H,S,32]
// GEMM M=4096, N=768 (q|k|v), K=256. BM=BN=64, BK=32, 256 threads, 4x4 micro.
// ---------------------------------------------------------------------------
__global__ __launch_bounds__(256) void qkv_kernel(
    const float* __restrict__ x,
    const float* __restrict__ wq, const float* __restrict__ bq,
    const float* __restrict__ wk, const float* __restrict__ bk,
    const float* __restrict__ wv, const float* __restrict__ bv)
{
    __shared__ float As[32][68];
    __shared__ float Bs[32][68];
    const int mt = blockIdx.x * 64;
    const int nt = blockIdx.y * 64;          // 0..767
    const int wsel = nt >> 8;                // 0=q,1=k,2=v
    const int nw = nt & 255;
    const float* W    = (wsel == 0) ? wq : ((wsel == 1) ? wk : wv);
    const float* bias = (wsel == 0) ? bq : ((wsel == 1) ? bk : bv);
    float* dst        = (wsel == 0) ? g_q : ((wsel == 1) ? g_k : g_v);

    const int tid = threadIdx.x;
    const int ty = tid >> 4, tx = tid & 15;
    float acc[4][4] = {};

    for (int k0 = 0; k0 < 256; k0 += 32) {
        for (int t = tid; t < 64 * 32; t += 256) {
            int m = t >> 5, kk = t & 31;
            As[kk][m] = x[(size_t)(mt + m) * 256 + k0 + kk];
            Bs[kk][m] = W[(size_t)(nw + m) * 256 + k0 + kk];
        }
        __syncthreads();
        #pragma unroll
        for (int kk = 0; kk < 32; kk++) {
            float4 a4 = *(const float4*)&As[kk][ty * 4];
            float4 b4 = *(const float4*)&Bs[kk][tx * 4];
            float a[4] = {a4.x, a4.y, a4.z, a4.w};
            float b[4] = {b4.x, b4.y, b4.z, b4.w};
            #pragma unroll
            for (int i = 0; i < 4; i++)
                #pragma unroll
                for (int j = 0; j < 4; j++)
                    acc[i][j] += a[i] * b[j];
        }
        __syncthreads();
    }
    #pragma unroll
    for (int i = 0; i < 4; i++) {
        int m = mt + ty * 4 + i;
        int bidx = m >> 11, s = m & 2047;
        #pragma unroll
        for (int j = 0; j < 4; j++) {
            int n = nw + tx * 4 + j;
            int h = n >> 5, dh = n & 31;
            dst[(((size_t)(bidx * HH + h) * SS + s) * DHD) + dh] = acc[i][j] + bias[n];
        }
    }
}

// ---------------------------------------------------------------------------
// Output projection: out = ctx @ wc^T + bc.  M=4096, N=256, K=256.
// ---------------------------------------------------------------------------
__global__ __launch_bounds__(256) void proj_kernel(
    const float* __restrict__ wc, const float* __restrict__ bc,
    float* __restrict__ out)
{
    __shared__ float As[32][68];
    __shared__ float Bs[32][68];
    const int mt = blockIdx.x * 64;
    const int nw = blockIdx.y * 64;
    const int tid = threadIdx.x;
    const int ty = tid >> 4, tx = tid & 15;
    float acc[4][4] = {};

    for (int k0 = 0; k0 < 256; k0 += 32) {
        for (int t = tid; t < 64 * 32; t += 256) {
            int m = t >> 5, kk = t & 31;
            As[kk][m] = g_ctx[(size_t)(mt + m) * 256 + k0 + kk];
            Bs[kk][m] = wc[(size_t)(nw + m) * 256 + k0 + kk];
        }
        __syncthreads();
        #pragma unroll
        for (int kk = 0; kk < 32; kk++) {
            float4 a4 = *(const float4*)&As[kk][ty * 4];
            float4 b4 = *(const float4*)&Bs[kk][tx * 4];
            float a[4] = {a4.x, a4.y, a4.z, a4.w};
            float b[4] = {b4.x, b4.y, b4.z, b4.w};
            #pragma unroll
            for (int i = 0; i < 4; i++)
                #pragma unroll
                for (int j = 0; j < 4; j++)
                    acc[i][j] += a[i] * b[j];
        }
        __syncthreads();
    }
    #pragma unroll
    for (int i = 0; i < 4; i++) {
        int m = mt + ty * 4 + i;
        #pragma unroll
        for (int j = 0; j < 4; j++) {
            int n = nw + tx * 4 + j;
            out[(size_t)m * 256 + n] = acc[i][j] + bc[n];
        }
    }
}

// ---------------------------------------------------------------------------
// Attention: one block per (b, 16-row q tile), loops over all 8 heads.
// Full 16x2048 score row kept in smem -> exact softmax, head-mean accumulated
// into the block-exclusive d_out slice (L2 resident), PV fused, P never hits
// HBM.
// smem layout (floats): sS[16*2048]=32768 | sKV[512*33]=16896 | sQ[16*33]=528
// ---------------------------------------------------------------------------
#define SMEM_FLOATS (32768 + 16896 + 528)

__global__ __launch_bounds__(256) void attn_kernel(float* __restrict__ attn_out)
{
    extern __shared__ float sm[];
    float* sS = sm;                     // 16 x 2048 scores/probs
    float* sK = sm + 32768;             // 512 x 33 K tile (aliased: V tile, reduce buf)
    float* sQ = sm + 32768 + 16896;     // 16 x 33
    __shared__ float s_invl[16];

    const int tid = threadIdx.x;
    const int b  = blockIdx.x >> 7;
    const int q0 = (blockIdx.x & 127) << 4;

    float* ap = attn_out + (size_t)(b * SS + q0) * SS;

    for (int h = 0; h < HH; h++) {
        const float* qb = g_q + ((size_t)(b * HH + h) * SS + q0) * DHD;
        const float* kb = g_k + (size_t)(b * HH + h) * SS * DHD;
        const float* vb = g_v + (size_t)(b * HH + h) * SS * DHD;

        // --- load Q tile (16x32) ---
        for (int t = tid; t < 16 * 32; t += 256)
            sQ[(t >> 5) * 33 + (t & 31)] = qb[t];

        // --- scores: S = Q K^T * scale, k-tiles of 512, micro 4q x 8k ---
        const int qg = tid >> 6;      // 0..3 -> 4 q rows each
        const int kg = tid & 63;      // k columns kg + 64*m
        const float scale = 0.17677669529663687f; // 1/sqrt(32)
        for (int kt = 0; kt < 4; kt++) {
            __syncthreads();  // prior consumers of sK (and sQ writers on kt==0) done
            for (int t = tid; t < 512 * 8; t += 256) {
                float4 v4 = *(const float4*)(kb + (size_t)kt * 16384 + (size_t)t * 4);
                int row = t >> 3, d4 = (t & 7) * 4;
                float* p = &sK[row * 33 + d4];
                p[0] = v4.x; p[1] = v4.y; p[2] = v4.z; p[3] = v4.w;
            }
            __syncthreads();
            float acc[4][8] = {};
            #pragma unroll
            for (int d = 0; d < 32; d++) {
                float a[4], bv[8];
                #pragma unroll
                for (int i = 0; i < 4; i++) a[i] = sQ[(qg * 4 + i) * 33 + d];
                #pragma unroll
                for (int m = 0; m < 8; m++) bv[m] = sK[(kg + 64 * m) * 33 + d];
                #pragma unroll
                for (int i = 0; i < 4; i++)
                    #pragma unroll
                    for (int m = 0; m < 8; m++)
                        acc[i][m] += a[i] * bv[m];
            }
            #pragma unroll
            for (int i = 0; i < 4; i++)
                #pragma unroll
                for (int m = 0; m < 8; m++)
                    sS[(qg * 4 + i) * 2048 + kt * 512 + kg + 64 * m] = acc[i][m] * scale;
        }
        __syncthreads();

        // --- softmax over full row (exact, in smem) ---
        {
            const int row = tid >> 4, j = tid & 15;   // 16 threads per row
            float4* r4 = (float4*)(sS + row * 2048);
            float mx = -1e30f;
            for (int k = j; k < 512; k += 16) {
                float4 v = r4[k];
                mx = fmaxf(mx, fmaxf(fmaxf(v.x, v.y), fmaxf(v.z, v.w)));
            }
            #pragma unroll
            for (int o = 8; o; o >>= 1) mx = fmaxf(mx, __shfl_xor_sync(0xffffffffu, mx, o));
            float sum = 0.f;
            for (int k = j; k < 512; k += 16) {
                float4 v = r4[k];
                v.x = __expf(v.x - mx); v.y = __expf(v.y - mx);
                v.z = __expf(v.z - mx); v.w = __expf(v.w - mx);
                sum += v.x + v.y + v.z + v.w;
                r4[k] = v;
            }
            #pragma unroll
            for (int o = 8; o; o >>= 1) sum += __shfl_xor_sync(0xffffffffu, sum, o);
            if (j == 0) s_invl[row] = 1.0f / sum;
        }
        __syncthreads();

        // --- accumulate head-mean attention into d_out slice (block-exclusive) ---
        {
            const float4* s4 = (const float4*)sS;
            float4* a4 = (float4*)ap;
            for (int t = tid; t < 16 * 512; t += 256) {
                int r = t >> 9;
                float f = s_invl[r] * 0.125f;
                float4 v = s4[t];
                v.x *= f; v.y *= f; v.z *= f; v.w *= f;
                if (h == 0) {
                    a4[t] = v;
                } else {
                    float4 o = a4[t];
                    o.x += v.x; o.y += v.y; o.z += v.z; o.w += v.w;
                    a4[t] = o;
                }
            }
        }

        // --- PV: O = P V, 4 phases of 512 k, micro 4q x 4d, k split 8 ways ---
        float accO[4][4] = {};
        const int qg2 = tid >> 6;          // 4 q rows
        const int ks  = (tid >> 3) & 7;    // k stripe (mod 8)
        const int dg  = tid & 7;           // 4 d cols
        for (int p = 0; p < 4; p++) {
            __syncthreads();  // previous phase consumers of sK done
            for (int t = tid; t < 512 * 8; t += 256) {
                float4 v4 = *(const float4*)(vb + (size_t)p * 16384 + (size_t)t * 4);
                int row = t >> 3, d4 = (t & 7) * 4;
                float* pp = &sK[row * 33 + d4];
                pp[0] = v4.x; pp[1] = v4.y; pp[2] = v4.z; pp[3] = v4.w;
            }
            __syncthreads();
            #pragma unroll 4
            for (int kk = 0; kk < 64; kk++) {
                int k = kk * 8 + ks;
                float pv[4], vv[4];
                #pragma unroll
                for (int i = 0; i < 4; i++) pv[i] = sS[(qg2 * 4 + i) * 2048 + p * 512 + k];
                #pragma unroll
                for (int j = 0; j < 4; j++) vv[j] = sK[k * 33 + dg * 4 + j];
                #pragma unroll
                for (int i = 0; i < 4; i++)
                    #pragma unroll
                    for (int j = 0; j < 4; j++)
                        accO[i][j] += pv[i] * vv[j];
            }
        }
        __syncthreads();
        // reduce the 8 k-stripes via smem (alias sK region)
        float* sRed = sK;
        #pragma unroll
        for (int i = 0; i < 4; i++)
            #pragma unroll
            for (int j = 0; j < 4; j++)
                sRed[((qg2 * 4 + i) * 32 + dg * 4 + j) * 8 + ks] = accO[i][j];
        __syncthreads();
        for (int o = tid; o < 512; o += 256) {
            int r = o >> 5, d = o & 31;
            float s = 0.f;
            #pragma unroll
            for (int e = 0; e < 8; e++) s += sRed[o * 8 + e];
            g_ctx[(size_t)(b * SS + q0 + r) * DD + h * DHD + d] = s * s_invl[r];
        }
        __syncthreads();  // protect sRed/sQ/sS before next head
    }
}

// ---------------------------------------------------------------------------
extern "C" void kernel_launch(void* const* d_in, const int* in_sizes, int n_in,
                              void* d_out, int out_size)
{
    const float* x  = (const float*)d_in[0];
    const float* wq = (const float*)d_in[1];
    const float* bq = (const float*)d_in[2];
    const float* wk = (const float*)d_in[3];
    const float* bk = (const float*)d_in[4];
    const float* wv = (const float*)d_in[5];
    const float* bv = (const float*)d_in[6];
    const float* wc = (const float*)d_in[7];
    const float* bc = (const float*)d_in[8];

    float* out  = (float*)d_out;
    float* attn = out + (size_t)BB * SS * DD;   // [B,S,S] region after [B,S,D]

    qkv_kernel<<<dim3(64, 12), 256>>>(x, wq, bq, wk, bk, wv, bv);

    cudaFuncSetAttribute(attn_kernel,
                         cudaFuncAttributeMaxDynamicSharedMemorySize,
                         SMEM_FLOATS * (int)sizeof(float));
    attn_kernel<<<256, 256, SMEM_FLOATS * sizeof(float)>>>(attn);

    proj_kernel<<<dim3(64, 4), 256>>>(wc, bc, out);
}